// round 11
// baseline (speedup 1.0000x reference)
#include <cuda_runtime.h>
#include <cstdint>

#define NTS    2048
#define KXV    256
#define NYV    8192
#define CSZ    8
#define NTH    1024
#define CHUNK  1024
#define GSTEP  4            /* steps between cross-CTA exchanges */
#define GL     (4*GSTEP)    /* 16 left ghosts  */
#define GR     (8*GSTEP)    /* 32 right ghosts */
#define NG     (GL+GR)      /* 48 */
#define EXT    (GL+CHUNK+GR)
#define GBASE  704          /* ghost duty on warps 22-23 (t in [704,752)) */
#define XBASE  768          /* X duty on warps 24-31 (highest arbiter priority) */

__device__ __forceinline__ uint32_t s2u(const void* p){
    return (uint32_t)__cvta_generic_to_shared(p);
}
__device__ __forceinline__ uint32_t mapa_u32(uint32_t la, uint32_t rank){
    uint32_t ra;
    asm("mapa.shared::cluster.u32 %0, %1, %2;" : "=r"(ra) : "r"(la), "r"(rank));
    return ra;
}
__device__ __forceinline__ void mbar_init(uint32_t a, uint32_t cnt){
    asm volatile("mbarrier.init.shared.b64 [%0], %1;" :: "r"(a), "r"(cnt) : "memory");
}
__device__ __forceinline__ void remote_st(uint32_t ra, float v){
    asm volatile("st.shared::cluster.f32 [%0], %1;" :: "r"(ra), "f"(v) : "memory");
}
__device__ __forceinline__ void remote_arrive(uint32_t ra){
    asm volatile("mbarrier.arrive.release.cluster.shared::cluster.b64 _, [%0];"
                 :: "r"(ra) : "memory");
}
__device__ __forceinline__ void mbar_wait(uint32_t a, uint32_t parity){
    asm volatile(
        "{\n\t"
        ".reg .pred P;\n"
        "WL_%=:\n\t"
        "mbarrier.try_wait.parity.acquire.cluster.shared::cta.b64 P, [%0], %1;\n\t"
        "@!P bra WL_%=;\n\t"
        "}"
        :: "r"(a), "r"(parity) : "memory");
}

__global__ __launch_bounds__(NTH, 1) __cluster_dims__(CSZ, 1, 1)
void lorenz96_kernel(const float* __restrict__ X0,
                     const float* __restrict__ Y0,
                     const float* __restrict__ coupling,
                     const float* __restrict__ pF,
                     const float* __restrict__ ph,
                     const float* __restrict__ pc,
                     const float* __restrict__ pdt,
                     float* __restrict__ xhist,
                     float* __restrict__ yhist)
{
    __shared__ float sYe[2][EXT + 3];   // 1 left pad + EXT + 2 right pads
    __shared__ float sX [2][KXV];
    __shared__ float mbxL[2][GL];
    __shared__ float mbxR[2][GR];
    __shared__ __align__(8) unsigned long long mbarL[2];
    __shared__ __align__(8) unsigned long long mbarR[2];

    const int t = threadIdx.x;
    const bool isX = (t >= XBASE);      // X duty on warps 24-31 (hi-wid = hi priority)
    const int  xk  = t - XBASE;         // X variable index for X threads

    uint32_t rank;
    asm("mov.u32 %0, %%cluster_ctarank;" : "=r"(rank));
    const uint32_t lrank = (rank + CSZ - 1) % CSZ;
    const uint32_t rrank = (rank + 1) % CSZ;

    const float F  = *pF;
    const float h  = *ph;
    const float c  = *pc;
    const float dt = *pdt;

    // frozen bit-exact constant recipe
    const float a      = __fmul_rn(__fmul_rn(-1.0f, c), 32.0f);
    const float hcJ    = __fdiv_rn(__fmul_rn(h, c), 32.0f);
    const float halfdt = __fmul_rn(0.5f, dt);
    const float dt6    = __fdiv_rn(dt, 6.0f);

    const int jg  = (int)rank * CHUNK + t;
    const int xiO = jg >> 5;
    const int xo  = GL + t;

    // ghost duty: threads [GBASE, GBASE+NG)  (warps 22-23, non-X)
    const bool hasG = (t >= GBASE) && (t < GBASE + NG);
    const int  gi   = t - GBASE;
    const int  gx   = hasG ? ((gi < GL) ? gi : (GL + CHUNK + (gi - GL))) : 0;
    const int  gg   = ((int)rank * CHUNK + gx - GL + NYV) & (NYV - 1);
    const int  xiG  = gg >> 5;

    if (t == 0) {
        #pragma unroll
        for (int b = 0; b < 2; b++) {
            mbar_init(s2u(&mbarL[b]), GL);
            mbar_init(s2u(&mbarR[b]), GR);
        }
        sYe[0][0] = 0.f;        sYe[1][0] = 0.f;
        sYe[0][EXT+1] = 0.f;    sYe[1][EXT+1] = 0.f;
        sYe[0][EXT+2] = 0.f;    sYe[1][EXT+2] = 0.f;
    }
    __syncthreads();
    asm volatile("barrier.cluster.arrive.aligned;" ::: "memory");
    asm volatile("barrier.cluster.wait.aligned;"   ::: "memory");

    uint32_t raR_d = 0, raR_b = 0, raL_d = 0, raL_b = 0;
    if (t < GR) {                       // my first GR owned -> LEFT neighbor's right ghosts
        raR_d = mapa_u32(s2u(&mbxR[0][t]), lrank);
        raR_b = mapa_u32(s2u(&mbarR[0]),   lrank);
    }
    if (t >= CHUNK - GL) {              // my last GL owned -> RIGHT neighbor's left ghosts
        raL_d = mapa_u32(s2u(&mbxL[0][t - (CHUNK - GL)]), rrank);
        raL_b = mapa_u32(s2u(&mbarL[0]),                  rrank);
    }

    // ---- state init (row 0) ----
    float yb = Y0[jg];
    float yc = yb, d1 = 0.f, d2 = 0.f;
    yhist[jg] = yb;
    sYe[0][xo + 1] = yb;

    float gyb = 0.f, gyc = 0.f, gd1 = 0.f, gd2 = 0.f;
    if (hasG) {
        gyb = Y0[gg];
        gyc = gyb;
        sYe[0][gx + 1] = gyb;
    }

    float xb = 0.f, xc = 0.f, xd1 = 0.f, xd2 = 0.f, coup_next = 0.f;
    if (isX) {
        xb = X0[xk]; xc = xb;
        sX[0][xk] = xb;
        coup_next = coupling[xk];
        if (rank == 0) xhist[xk] = xb;
    }
    __syncthreads();

    int xrnd = 0;

    for (int n = 1; n < NTS; n++) {
        const float coup = coup_next;
        if (isX && n < NTS - 1) coup_next = coupling[n * KXV + xk];

        #pragma unroll
        for (int s = 0; s < 4; s++) {
            const int rb = s & 1;
            const int wb = rb ^ 1;

            // owned cell derivative
            const float ym1 = sYe[rb][xo];
            const float yp1 = sYe[rb][xo + 2];
            const float yp2 = sYe[rb][xo + 3];
            const float xs  = sX[rb][xiO];
            const float t1 = __fsub_rn(yp2, ym1);
            const float t2 = __fmul_rn(a, yp1);
            const float t4 = __fmul_rn(c, yc);
            const float t5 = __fmaf_rn(t2, t1, -t4);
            const float dn = __fmaf_rn(hcJ, xs, t5);

            // ghost cell derivative
            float gdn = 0.f;
            if (hasG) {
                const float gm1 = sYe[rb][gx];
                const float gp1 = sYe[rb][gx + 2];
                const float gp2 = sYe[rb][gx + 3];
                const float gxs = sX[rb][xiG];
                const float g1 = __fsub_rn(gp2, gm1);
                const float g2 = __fmul_rn(a, gp1);
                const float g4 = __fmul_rn(c, gyc);
                const float g5 = __fmaf_rn(g2, g1, -g4);
                gdn = __fmaf_rn(hcJ, gxs, g5);
            }

            // X derivative
            float xdn = 0.f;
            if (isX) {
                const float xm2 = sX[rb][(xk + KXV - 2) & (KXV - 1)];
                const float xm1 = sX[rb][(xk + KXV - 1) & (KXV - 1)];
                const float xp1 = sX[rb][(xk + 1) & (KXV - 1)];
                const float u1 = __fsub_rn(xp1, xm2);
                const float u3 = __fmaf_rn(xm1, u1, -xc);
                const float u4 = __fadd_rn(u3, F);
                xdn = __fadd_rn(u4, coup);
            }

            // stage updates (frozen recipe)
            if (s == 0) {
                d1 = dn;                        yc  = __fmaf_rn(halfdt, dn,  yb);
                if (hasG) { gd1 = gdn;          gyc = __fmaf_rn(halfdt, gdn, gyb); }
                if (isX)  { xd1 = xdn;          xc  = __fmaf_rn(halfdt, xdn, xb); }
            } else if (s == 1) {
                d2 = dn;                        yc  = __fmaf_rn(halfdt, dn,  yb);
                if (hasG) { gd2 = gdn;          gyc = __fmaf_rn(halfdt, gdn, gyb); }
                if (isX)  { xd2 = xdn;          xc  = __fmaf_rn(halfdt, xdn, xb); }
            } else if (s == 2) {
                d2 = __fadd_rn(d2, dn);         yc  = __fmaf_rn(dt, dn,  yb);
                if (hasG) { gd2 = __fadd_rn(gd2, gdn); gyc = __fmaf_rn(dt, gdn, gyb); }
                if (isX)  { xd2 = __fadd_rn(xd2, xdn); xc  = __fmaf_rn(dt, xdn, xb); }
            } else {
                const float sA  = __fadd_rn(d1, dn);
                const float sum = __fmaf_rn(2.0f, d2, sA);
                yc = __fmaf_rn(dt6, sum, yb);  yb = yc;
                if (hasG) {
                    const float gA  = __fadd_rn(gd1, gdn);
                    const float gsm = __fmaf_rn(2.0f, gd2, gA);
                    gyc = __fmaf_rn(dt6, gsm, gyb);  gyb = gyc;
                }
                if (isX) {
                    const float xA  = __fadd_rn(xd1, xdn);
                    const float xsm = __fmaf_rn(2.0f, xd2, xA);
                    xc = __fmaf_rn(dt6, xsm, xb);  xb = xc;
                }
            }

            sYe[wb][xo + 1] = yc;
            if (hasG) sYe[wb][gx + 1] = gyc;
            if (isX)  sX[wb][xk] = xc;
            __syncthreads();
        }

        // history row n
        yhist[(size_t)n * NYV + jg] = yc;
        if (isX && rank == 0) xhist[(size_t)n * KXV + xk] = xc;

        // ghost exchange every GSTEP steps
        if ((n & (GSTEP - 1)) == 0 && n < NTS - 1) {
            const int      buf = xrnd & 1;
            const uint32_t par = (uint32_t)((xrnd >> 1) & 1);

            if (t < GR) {
                remote_st(raR_d + (uint32_t)buf * (GR * 4), yc);
                remote_arrive(raR_b + (uint32_t)buf * 8);
            }
            if (t >= CHUNK - GL) {
                remote_st(raL_d + (uint32_t)buf * (GL * 4), yc);
                remote_arrive(raL_b + (uint32_t)buf * 8);
            }

            if (hasG) {
                if (gi < GL) {
                    mbar_wait(s2u(&mbarL[buf]), par);
                    gyb = mbxL[buf][gi];
                } else {
                    mbar_wait(s2u(&mbarR[buf]), par);
                    gyb = mbxR[buf][gi - GL];
                }
                gyc = gyb;
                sYe[0][gx + 1] = gyb;     // base buffer is buf0 at step start
            }
            xrnd++;
            __syncthreads();
        }
    }

    asm volatile("barrier.cluster.arrive.aligned;" ::: "memory");
    asm volatile("barrier.cluster.wait.aligned;"   ::: "memory");
}

extern "C" void kernel_launch(void* const* d_in, const int* in_sizes, int n_in,
                              void* d_out, int out_size)
{
    const float* X0  = (const float*)d_in[0];
    const float* Y0  = (const float*)d_in[1];
    const float* cp  = (const float*)d_in[2];
    const float* pF  = (const float*)d_in[3];
    const float* ph  = (const float*)d_in[4];
    // d_in[5] = b (unused by the math)
    const float* pc  = (const float*)d_in[6];
    const float* pdt = (const float*)d_in[7];

    float* out   = (float*)d_out;
    float* xhist = out;                       // [2048, 256]
    float* yhist = out + (size_t)NTS * KXV;   // [2048, 8192]

    lorenz96_kernel<<<CSZ, NTH>>>(X0, Y0, cp, pF, ph, pc, pdt, xhist, yhist);
}

// round 12
// speedup vs baseline: 1.4249x; 1.4249x over previous
#include <cuda_runtime.h>
#include <cstdint>

#define NTS    2048
#define KXV    256
#define NYV    8192
#define CSZ    8
#define NTH    1024
#define CHUNK  1024
#define GSTEP  4            /* steps between cross-CTA exchanges */
#define GL     (4*GSTEP)    /* 16 left ghosts  */
#define GR     (8*GSTEP)    /* 32 right ghosts */
#define NG     (GL+GR)      /* 48 */
#define EXT    (GL+CHUNK+GR)
#define GBASE  256          /* ghost duty on threads [256,304) — R9 placement */

__device__ __forceinline__ uint32_t s2u(const void* p){
    return (uint32_t)__cvta_generic_to_shared(p);
}
__device__ __forceinline__ uint32_t mapa_u32(uint32_t la, uint32_t rank){
    uint32_t ra;
    asm("mapa.shared::cluster.u32 %0, %1, %2;" : "=r"(ra) : "r"(la), "r"(rank));
    return ra;
}
__device__ __forceinline__ void mbar_init(uint32_t a, uint32_t cnt){
    asm volatile("mbarrier.init.shared.b64 [%0], %1;" :: "r"(a), "r"(cnt) : "memory");
}
__device__ __forceinline__ void remote_st(uint32_t ra, float v){
    asm volatile("st.shared::cluster.f32 [%0], %1;" :: "r"(ra), "f"(v) : "memory");
}
__device__ __forceinline__ void remote_arrive(uint32_t ra){
    asm volatile("mbarrier.arrive.release.cluster.shared::cluster.b64 _, [%0];"
                 :: "r"(ra) : "memory");
}
__device__ __forceinline__ void mbar_wait(uint32_t a, uint32_t parity){
    asm volatile(
        "{\n\t"
        ".reg .pred P;\n"
        "WL_%=:\n\t"
        "mbarrier.try_wait.parity.acquire.cluster.shared::cta.b64 P, [%0], %1;\n\t"
        "@!P bra WL_%=;\n\t"
        "}"
        :: "r"(a), "r"(parity) : "memory");
}

// One main-loop instantiation per warp class. All instantiations execute an
// IDENTICAL barrier sequence: 4 __syncthreads per step + 1 per exchange round.
// IS_X  : warps 0-7   — X duty + Y cell + right-edge remote sends (t < GR)
// HAS_G : warps 8-9   — ghost duty ([256,304)) + Y cell + exchange receives
// pure  : warps 10-31 — Y cell only + left-edge remote sends (t >= CHUNK-GL)
template<bool IS_X, bool HAS_G>
__device__ __forceinline__ void run_loop(
    const int t, const int jg, const int xo, const int xiO,
    const float a, const float hcJ, const float halfdt, const float dt6,
    const float F, const float c, const float dt,
    float yb, float yc,
    const bool hasG, const int gi, const int gx, const int xiG,
    float gyb, float gyc,
    float xb, float xc, float coup_next,
    const float* __restrict__ coupling,
    float* __restrict__ xhist, float* __restrict__ yhist,
    float (*sYe)[EXT + 3], float (*sX)[KXV],
    float (*mbxL)[GL], float (*mbxR)[GR],
    unsigned long long* mbarL, unsigned long long* mbarR,
    const uint32_t raR_d, const uint32_t raR_b,
    const uint32_t raL_d, const uint32_t raL_b,
    const uint32_t rank)
{
    float d1 = 0.f, d2 = 0.f;
    float gd1 = 0.f, gd2 = 0.f;
    float xd1 = 0.f, xd2 = 0.f;
    int xrnd = 0;

    for (int n = 1; n < NTS; n++) {
        float coup = 0.f;
        if constexpr (IS_X) {
            coup = coup_next;
            if (n < NTS - 1) coup_next = coupling[n * KXV + (t)];
        }

        #pragma unroll
        for (int s = 0; s < 4; s++) {
            const int rb = s & 1;
            const int wb = rb ^ 1;

            // owned cell derivative (frozen op order)
            const float ym1 = sYe[rb][xo];
            const float yp1 = sYe[rb][xo + 2];
            const float yp2 = sYe[rb][xo + 3];
            const float xs  = sX[rb][xiO];
            const float t1 = __fsub_rn(yp2, ym1);
            const float t2 = __fmul_rn(a, yp1);
            const float t4 = __fmul_rn(c, yc);
            const float t5 = __fmaf_rn(t2, t1, -t4);
            const float dn = __fmaf_rn(hcJ, xs, t5);

            float gdn = 0.f;
            if constexpr (HAS_G) {
                if (hasG) {
                    const float gm1 = sYe[rb][gx];
                    const float gp1 = sYe[rb][gx + 2];
                    const float gp2 = sYe[rb][gx + 3];
                    const float gxs = sX[rb][xiG];
                    const float g1 = __fsub_rn(gp2, gm1);
                    const float g2 = __fmul_rn(a, gp1);
                    const float g4 = __fmul_rn(c, gyc);
                    const float g5 = __fmaf_rn(g2, g1, -g4);
                    gdn = __fmaf_rn(hcJ, gxs, g5);
                }
            }

            float xdn = 0.f;
            if constexpr (IS_X) {
                const float xm2 = sX[rb][(t + KXV - 2) & (KXV - 1)];
                const float xm1 = sX[rb][(t + KXV - 1) & (KXV - 1)];
                const float xp1 = sX[rb][(t + 1) & (KXV - 1)];
                const float u1 = __fsub_rn(xp1, xm2);
                const float u3 = __fmaf_rn(xm1, u1, -xc);
                const float u4 = __fadd_rn(u3, F);
                xdn = __fadd_rn(u4, coup);
            }

            // stage updates (frozen recipe)
            if (s == 0) {
                d1 = dn;  yc = __fmaf_rn(halfdt, dn, yb);
                if constexpr (HAS_G) { if (hasG) { gd1 = gdn; gyc = __fmaf_rn(halfdt, gdn, gyb); } }
                if constexpr (IS_X)  { xd1 = xdn; xc = __fmaf_rn(halfdt, xdn, xb); }
            } else if (s == 1) {
                d2 = dn;  yc = __fmaf_rn(halfdt, dn, yb);
                if constexpr (HAS_G) { if (hasG) { gd2 = gdn; gyc = __fmaf_rn(halfdt, gdn, gyb); } }
                if constexpr (IS_X)  { xd2 = xdn; xc = __fmaf_rn(halfdt, xdn, xb); }
            } else if (s == 2) {
                d2 = __fadd_rn(d2, dn);  yc = __fmaf_rn(dt, dn, yb);
                if constexpr (HAS_G) { if (hasG) { gd2 = __fadd_rn(gd2, gdn); gyc = __fmaf_rn(dt, gdn, gyb); } }
                if constexpr (IS_X)  { xd2 = __fadd_rn(xd2, xdn); xc = __fmaf_rn(dt, xdn, xb); }
            } else {
                const float sA  = __fadd_rn(d1, dn);
                const float sum = __fmaf_rn(2.0f, d2, sA);
                yc = __fmaf_rn(dt6, sum, yb);  yb = yc;
                if constexpr (HAS_G) {
                    if (hasG) {
                        const float gA  = __fadd_rn(gd1, gdn);
                        const float gsm = __fmaf_rn(2.0f, gd2, gA);
                        gyc = __fmaf_rn(dt6, gsm, gyb);  gyb = gyc;
                    }
                }
                if constexpr (IS_X) {
                    const float xA  = __fadd_rn(xd1, xdn);
                    const float xsm = __fmaf_rn(2.0f, xd2, xA);
                    xc = __fmaf_rn(dt6, xsm, xb);  xb = xc;
                }
            }

            sYe[wb][xo + 1] = yc;
            if constexpr (HAS_G) { if (hasG) sYe[wb][gx + 1] = gyc; }
            if constexpr (IS_X)  sX[wb][t] = xc;
            __syncthreads();                        // barrier 1..4 of step
        }

        // history row n
        yhist[(size_t)n * NYV + jg] = yc;
        if constexpr (IS_X) { if (rank == 0) xhist[(size_t)n * KXV + t] = xc; }

        // ghost exchange every GSTEP steps (identical condition in all paths)
        if ((n & (GSTEP - 1)) == 0 && n < NTS - 1) {
            const int      buf = xrnd & 1;
            const uint32_t par = (uint32_t)((xrnd >> 1) & 1);

            if constexpr (IS_X) {                   // senders t < GR live in warps 0-7
                if (t < GR) {
                    remote_st(raR_d + (uint32_t)buf * (GR * 4), yc);
                    remote_arrive(raR_b + (uint32_t)buf * 8);
                }
            }
            if constexpr (!IS_X && !HAS_G) {        // senders t >= CHUNK-GL live in warp 31
                if (t >= CHUNK - GL) {
                    remote_st(raL_d + (uint32_t)buf * (GL * 4), yc);
                    remote_arrive(raL_b + (uint32_t)buf * 8);
                }
            }
            if constexpr (HAS_G) {
                if (hasG) {
                    if (gi < GL) {
                        mbar_wait(s2u(&mbarL[buf]), par);
                        gyb = mbxL[buf][gi];
                    } else {
                        mbar_wait(s2u(&mbarR[buf]), par);
                        gyb = mbxR[buf][gi - GL];
                    }
                    gyc = gyb;
                    sYe[0][gx + 1] = gyb;           // base buffer is buf0 at step start
                }
            }
            xrnd++;
            __syncthreads();                        // exchange barrier
        }
    }
}

__global__ __launch_bounds__(NTH, 1) __cluster_dims__(CSZ, 1, 1)
void lorenz96_kernel(const float* __restrict__ X0,
                     const float* __restrict__ Y0,
                     const float* __restrict__ coupling,
                     const float* __restrict__ pF,
                     const float* __restrict__ ph,
                     const float* __restrict__ pc,
                     const float* __restrict__ pdt,
                     float* __restrict__ xhist,
                     float* __restrict__ yhist)
{
    __shared__ float sYe[2][EXT + 3];   // 1 left pad + EXT + 2 right pads
    __shared__ float sX [2][KXV];
    __shared__ float mbxL[2][GL];
    __shared__ float mbxR[2][GR];
    __shared__ __align__(8) unsigned long long mbarL[2];
    __shared__ __align__(8) unsigned long long mbarR[2];

    const int t = threadIdx.x;
    const bool isX = (t < KXV);

    uint32_t rank;
    asm("mov.u32 %0, %%cluster_ctarank;" : "=r"(rank));
    const uint32_t lrank = (rank + CSZ - 1) % CSZ;
    const uint32_t rrank = (rank + 1) % CSZ;

    const float F  = *pF;
    const float h  = *ph;
    const float c  = *pc;
    const float dt = *pdt;

    // frozen bit-exact constant recipe
    const float a      = __fmul_rn(__fmul_rn(-1.0f, c), 32.0f);
    const float hcJ    = __fdiv_rn(__fmul_rn(h, c), 32.0f);
    const float halfdt = __fmul_rn(0.5f, dt);
    const float dt6    = __fdiv_rn(dt, 6.0f);

    const int jg  = (int)rank * CHUNK + t;
    const int xiO = jg >> 5;
    const int xo  = GL + t;

    // ghost duty: threads [GBASE, GBASE+NG)
    const bool hasG = (t >= GBASE) && (t < GBASE + NG);
    const int  gi   = t - GBASE;
    const int  gx   = hasG ? ((gi < GL) ? gi : (GL + CHUNK + (gi - GL))) : 0;
    const int  gg   = ((int)rank * CHUNK + gx - GL + NYV) & (NYV - 1);
    const int  xiG  = gg >> 5;

    if (t == 0) {
        #pragma unroll
        for (int b = 0; b < 2; b++) {
            mbar_init(s2u(&mbarL[b]), GL);
            mbar_init(s2u(&mbarR[b]), GR);
        }
        sYe[0][0] = 0.f;        sYe[1][0] = 0.f;
        sYe[0][EXT+1] = 0.f;    sYe[1][EXT+1] = 0.f;
        sYe[0][EXT+2] = 0.f;    sYe[1][EXT+2] = 0.f;
    }
    __syncthreads();
    asm volatile("barrier.cluster.arrive.aligned;" ::: "memory");
    asm volatile("barrier.cluster.wait.aligned;"   ::: "memory");

    uint32_t raR_d = 0, raR_b = 0, raL_d = 0, raL_b = 0;
    if (t < GR) {
        raR_d = mapa_u32(s2u(&mbxR[0][t]), lrank);
        raR_b = mapa_u32(s2u(&mbarR[0]),   lrank);
    }
    if (t >= CHUNK - GL) {
        raL_d = mapa_u32(s2u(&mbxL[0][t - (CHUNK - GL)]), rrank);
        raL_b = mapa_u32(s2u(&mbarL[0]),                  rrank);
    }

    // ---- state init (row 0) ----
    float yb = Y0[jg];
    float yc = yb;
    yhist[jg] = yb;
    sYe[0][xo + 1] = yb;

    float gyb = 0.f, gyc = 0.f;
    if (hasG) {
        gyb = Y0[gg];
        gyc = gyb;
        sYe[0][gx + 1] = gyb;
    }

    float xb = 0.f, xc = 0.f, coup_next = 0.f;
    if (isX) {
        xb = X0[t]; xc = xb;
        sX[0][t] = xb;
        coup_next = coupling[t];
        if (rank == 0) xhist[t] = xb;
    }
    __syncthreads();

    const int wid = t >> 5;
    if (wid < 8) {
        run_loop<true, false>(t, jg, xo, xiO, a, hcJ, halfdt, dt6, F, c, dt,
                              yb, yc, false, 0, 0, 0, 0.f, 0.f,
                              xb, xc, coup_next, coupling, xhist, yhist,
                              sYe, sX, mbxL, mbxR, mbarL, mbarR,
                              raR_d, raR_b, raL_d, raL_b, rank);
    } else if (wid < 10) {
        run_loop<false, true>(t, jg, xo, xiO, a, hcJ, halfdt, dt6, F, c, dt,
                              yb, yc, hasG, gi, gx, xiG, gyb, gyc,
                              0.f, 0.f, 0.f, coupling, xhist, yhist,
                              sYe, sX, mbxL, mbxR, mbarL, mbarR,
                              raR_d, raR_b, raL_d, raL_b, rank);
    } else {
        run_loop<false, false>(t, jg, xo, xiO, a, hcJ, halfdt, dt6, F, c, dt,
                               yb, yc, false, 0, 0, 0, 0.f, 0.f,
                               0.f, 0.f, 0.f, coupling, xhist, yhist,
                               sYe, sX, mbxL, mbxR, mbarL, mbarR,
                               raR_d, raR_b, raL_d, raL_b, rank);
    }

    asm volatile("barrier.cluster.arrive.aligned;" ::: "memory");
    asm volatile("barrier.cluster.wait.aligned;"   ::: "memory");
}

extern "C" void kernel_launch(void* const* d_in, const int* in_sizes, int n_in,
                              void* d_out, int out_size)
{
    const float* X0  = (const float*)d_in[0];
    const float* Y0  = (const float*)d_in[1];
    const float* cp  = (const float*)d_in[2];
    const float* pF  = (const float*)d_in[3];
    const float* ph  = (const float*)d_in[4];
    // d_in[5] = b (unused by the math)
    const float* pc  = (const float*)d_in[6];
    const float* pdt = (const float*)d_in[7];

    float* out   = (float*)d_out;
    float* xhist = out;                       // [2048, 256]
    float* yhist = out + (size_t)NTS * KXV;   // [2048, 8192]

    lorenz96_kernel<<<CSZ, NTH>>>(X0, Y0, cp, pF, ph, pc, pdt, xhist, yhist);
}

// round 13
// speedup vs baseline: 1.8404x; 1.2916x over previous
#include <cuda_runtime.h>
#include <cstdint>

#define NTS    2048
#define KXV    256
#define NYV    8192
#define CSZ    8
#define NTH    1024
#define CHUNK  1024
#define GSTEP  8            /* steps between cross-CTA exchanges */
#define GL     (4*GSTEP)    /* 32 left ghosts  */
#define GR     (8*GSTEP)    /* 64 right ghosts */
#define NG     (GL+GR)      /* 96 */
#define EXT    (GL+CHUNK+GR)
#define GBASE  256          /* ghost duty on threads [256,352) — warps 8-10 */

__device__ __forceinline__ uint32_t s2u(const void* p){
    return (uint32_t)__cvta_generic_to_shared(p);
}
__device__ __forceinline__ uint32_t mapa_u32(uint32_t la, uint32_t rank){
    uint32_t ra;
    asm("mapa.shared::cluster.u32 %0, %1, %2;" : "=r"(ra) : "r"(la), "r"(rank));
    return ra;
}
__device__ __forceinline__ void mbar_init(uint32_t a, uint32_t cnt){
    asm volatile("mbarrier.init.shared.b64 [%0], %1;" :: "r"(a), "r"(cnt) : "memory");
}
__device__ __forceinline__ void remote_st(uint32_t ra, float v){
    asm volatile("st.shared::cluster.f32 [%0], %1;" :: "r"(ra), "f"(v) : "memory");
}
__device__ __forceinline__ void remote_arrive(uint32_t ra){
    asm volatile("mbarrier.arrive.release.cluster.shared::cluster.b64 _, [%0];"
                 :: "r"(ra) : "memory");
}
__device__ __forceinline__ void mbar_wait(uint32_t a, uint32_t parity){
    asm volatile(
        "{\n\t"
        ".reg .pred P;\n"
        "WL_%=:\n\t"
        "mbarrier.try_wait.parity.acquire.cluster.shared::cta.b64 P, [%0], %1;\n\t"
        "@!P bra WL_%=;\n\t"
        "}"
        :: "r"(a), "r"(parity) : "memory");
}

__global__ __launch_bounds__(NTH, 1) __cluster_dims__(CSZ, 1, 1)
void lorenz96_kernel(const float* __restrict__ X0,
                     const float* __restrict__ Y0,
                     const float* __restrict__ coupling,
                     const float* __restrict__ pF,
                     const float* __restrict__ ph,
                     const float* __restrict__ pc,
                     const float* __restrict__ pdt,
                     float* __restrict__ xhist,
                     float* __restrict__ yhist)
{
    __shared__ float sYe[2][EXT + 3];   // 1 left pad + EXT + 2 right pads
    __shared__ float sX [2][KXV];
    __shared__ float mbxL[2][GL];
    __shared__ float mbxR[2][GR];
    __shared__ __align__(8) unsigned long long mbarL[2];
    __shared__ __align__(8) unsigned long long mbarR[2];

    const int t = threadIdx.x;
    const bool isX = (t < KXV);

    uint32_t rank;
    asm("mov.u32 %0, %%cluster_ctarank;" : "=r"(rank));
    const uint32_t lrank = (rank + CSZ - 1) % CSZ;
    const uint32_t rrank = (rank + 1) % CSZ;

    const float F  = *pF;
    const float h  = *ph;
    const float c  = *pc;
    const float dt = *pdt;

    // frozen bit-exact constant recipe
    const float a      = __fmul_rn(__fmul_rn(-1.0f, c), 32.0f);
    const float hcJ    = __fdiv_rn(__fmul_rn(h, c), 32.0f);
    const float halfdt = __fmul_rn(0.5f, dt);
    const float dt6    = __fdiv_rn(dt, 6.0f);

    const int jg  = (int)rank * CHUNK + t;
    const int xiO = jg >> 5;
    const int xo  = GL + t;

    // ghost duty: threads [GBASE, GBASE+NG)
    const bool hasG = (t >= GBASE) && (t < GBASE + NG);
    const int  gi   = t - GBASE;
    const int  gx   = hasG ? ((gi < GL) ? gi : (GL + CHUNK + (gi - GL))) : 0;
    const int  gg   = ((int)rank * CHUNK + gx - GL + NYV) & (NYV - 1);
    const int  xiG  = gg >> 5;

    if (t == 0) {
        #pragma unroll
        for (int b = 0; b < 2; b++) {
            mbar_init(s2u(&mbarL[b]), GL);
            mbar_init(s2u(&mbarR[b]), GR);
        }
        sYe[0][0] = 0.f;        sYe[1][0] = 0.f;
        sYe[0][EXT+1] = 0.f;    sYe[1][EXT+1] = 0.f;
        sYe[0][EXT+2] = 0.f;    sYe[1][EXT+2] = 0.f;
    }
    __syncthreads();
    asm volatile("barrier.cluster.arrive.aligned;" ::: "memory");
    asm volatile("barrier.cluster.wait.aligned;"   ::: "memory");

    uint32_t raR_d = 0, raR_b = 0, raL_d = 0, raL_b = 0;
    if (t < GR) {                       // my first GR owned -> LEFT neighbor's right ghosts
        raR_d = mapa_u32(s2u(&mbxR[0][t]), lrank);
        raR_b = mapa_u32(s2u(&mbarR[0]),   lrank);
    }
    if (t >= CHUNK - GL) {              // my last GL owned -> RIGHT neighbor's left ghosts
        raL_d = mapa_u32(s2u(&mbxL[0][t - (CHUNK - GL)]), rrank);
        raL_b = mapa_u32(s2u(&mbarL[0]),                  rrank);
    }

    // ---- state init (row 0) ----
    float yb = Y0[jg];
    float yc = yb, d1 = 0.f, d2 = 0.f;
    yhist[jg] = yb;
    sYe[0][xo + 1] = yb;

    float gyb = 0.f, gyc = 0.f, gd1 = 0.f, gd2 = 0.f;
    if (hasG) {
        gyb = Y0[gg];
        gyc = gyb;
        sYe[0][gx + 1] = gyb;
    }

    float xb = 0.f, xc = 0.f, xd1 = 0.f, xd2 = 0.f, coup_next = 0.f;
    if (isX) {
        xb = X0[t]; xc = xb;
        sX[0][t] = xb;
        coup_next = coupling[t];
        if (rank == 0) xhist[t] = xb;
    }
    __syncthreads();

    int xrnd = 0;

    for (int n = 1; n < NTS; n++) {
        const float coup = coup_next;
        if (isX && n < NTS - 1) coup_next = coupling[n * KXV + t];

        // exchange-round bookkeeping (used by early sends at s=3 and by receives)
        const bool     exch = ((n & (GSTEP - 1)) == 0) && (n < NTS - 1);
        const int      buf  = xrnd & 1;
        const uint32_t par  = (uint32_t)((xrnd >> 1) & 1);

        #pragma unroll
        for (int s = 0; s < 4; s++) {
            const int rb = s & 1;
            const int wb = rb ^ 1;

            // owned cell derivative (frozen op order)
            const float ym1 = sYe[rb][xo];
            const float yp1 = sYe[rb][xo + 2];
            const float yp2 = sYe[rb][xo + 3];
            const float xs  = sX[rb][xiO];
            const float t1 = __fsub_rn(yp2, ym1);
            const float t2 = __fmul_rn(a, yp1);
            const float t4 = __fmul_rn(c, yc);
            const float t5 = __fmaf_rn(t2, t1, -t4);
            const float dn = __fmaf_rn(hcJ, xs, t5);

            // ghost cell derivative
            float gdn = 0.f;
            if (hasG) {
                const float gm1 = sYe[rb][gx];
                const float gp1 = sYe[rb][gx + 2];
                const float gp2 = sYe[rb][gx + 3];
                const float gxs = sX[rb][xiG];
                const float g1 = __fsub_rn(gp2, gm1);
                const float g2 = __fmul_rn(a, gp1);
                const float g4 = __fmul_rn(c, gyc);
                const float g5 = __fmaf_rn(g2, g1, -g4);
                gdn = __fmaf_rn(hcJ, gxs, g5);
            }

            // X derivative
            float xdn = 0.f;
            if (isX) {
                const float xm2 = sX[rb][(t + KXV - 2) & (KXV - 1)];
                const float xm1 = sX[rb][(t + KXV - 1) & (KXV - 1)];
                const float xp1 = sX[rb][(t + 1) & (KXV - 1)];
                const float u1 = __fsub_rn(xp1, xm2);
                const float u3 = __fmaf_rn(xm1, u1, -xc);
                const float u4 = __fadd_rn(u3, F);
                xdn = __fadd_rn(u4, coup);
            }

            // stage updates (frozen recipe)
            if (s == 0) {
                d1 = dn;                        yc  = __fmaf_rn(halfdt, dn,  yb);
                if (hasG) { gd1 = gdn;          gyc = __fmaf_rn(halfdt, gdn, gyb); }
                if (isX)  { xd1 = xdn;          xc  = __fmaf_rn(halfdt, xdn, xb); }
            } else if (s == 1) {
                d2 = dn;                        yc  = __fmaf_rn(halfdt, dn,  yb);
                if (hasG) { gd2 = gdn;          gyc = __fmaf_rn(halfdt, gdn, gyb); }
                if (isX)  { xd2 = xdn;          xc  = __fmaf_rn(halfdt, xdn, xb); }
            } else if (s == 2) {
                d2 = __fadd_rn(d2, dn);         yc  = __fmaf_rn(dt, dn,  yb);
                if (hasG) { gd2 = __fadd_rn(gd2, gdn); gyc = __fmaf_rn(dt, gdn, gyb); }
                if (isX)  { xd2 = __fadd_rn(xd2, xdn); xc  = __fmaf_rn(dt, xdn, xb); }
            } else {
                const float sA  = __fadd_rn(d1, dn);
                const float sum = __fmaf_rn(2.0f, d2, sA);
                yc = __fmaf_rn(dt6, sum, yb);  yb = yc;
                if (hasG) {
                    const float gA  = __fadd_rn(gd1, gdn);
                    const float gsm = __fmaf_rn(2.0f, gd2, gA);
                    gyc = __fmaf_rn(dt6, gsm, gyb);  gyb = gyc;
                }
                if (isX) {
                    const float xA  = __fadd_rn(xd1, xdn);
                    const float xsm = __fmaf_rn(2.0f, xd2, xA);
                    xc = __fmaf_rn(dt6, xsm, xb);  xb = xc;
                }
            }

            sYe[wb][xo + 1] = yc;
            if (hasG) sYe[wb][gx + 1] = gyc;
            if (isX)  sX[wb][t] = xc;

            // EARLY SEND: on exchange steps, launch remote edge stores right
            // after the post-step base (yc) is computed, so the ~215-cyc DSMEM
            // latency overlaps the step-final barrier + history write.
            if (s == 3 && exch) {
                if (t < GR) {
                    remote_st(raR_d + (uint32_t)buf * (GR * 4), yc);
                    remote_arrive(raR_b + (uint32_t)buf * 8);
                }
                if (t >= CHUNK - GL) {
                    remote_st(raL_d + (uint32_t)buf * (GL * 4), yc);
                    remote_arrive(raL_b + (uint32_t)buf * 8);
                }
            }
            __syncthreads();
        }

        // history row n
        yhist[(size_t)n * NYV + jg] = yc;
        if (isX && rank == 0) xhist[(size_t)n * KXV + t] = xc;

        // ghost receive every GSTEP steps
        if (exch) {
            if (hasG) {
                if (gi < GL) {
                    mbar_wait(s2u(&mbarL[buf]), par);
                    gyb = mbxL[buf][gi];
                } else {
                    mbar_wait(s2u(&mbarR[buf]), par);
                    gyb = mbxR[buf][gi - GL];
                }
                gyc = gyb;
                sYe[0][gx + 1] = gyb;     // base buffer is buf0 at step start
            }
            xrnd++;
            __syncthreads();
        }
    }

    asm volatile("barrier.cluster.arrive.aligned;" ::: "memory");
    asm volatile("barrier.cluster.wait.aligned;"   ::: "memory");
}

extern "C" void kernel_launch(void* const* d_in, const int* in_sizes, int n_in,
                              void* d_out, int out_size)
{
    const float* X0  = (const float*)d_in[0];
    const float* Y0  = (const float*)d_in[1];
    const float* cp  = (const float*)d_in[2];
    const float* pF  = (const float*)d_in[3];
    const float* ph  = (const float*)d_in[4];
    // d_in[5] = b (unused by the math)
    const float* pc  = (const float*)d_in[6];
    const float* pdt = (const float*)d_in[7];

    float* out   = (float*)d_out;
    float* xhist = out;                       // [2048, 256]
    float* yhist = out + (size_t)NTS * KXV;   // [2048, 8192]

    lorenz96_kernel<<<CSZ, NTH>>>(X0, Y0, cp, pF, ph, pc, pdt, xhist, yhist);
}

// round 14
// speedup vs baseline: 2.1404x; 1.1630x over previous
#include <cuda_runtime.h>
#include <cstdint>

#define NTS    2048
#define KXV    256
#define NYV    8192
#define CSZ    8
#define NTH    1024
#define CHUNK  1024
#define NYT    512          /* Y-duty threads, 2 cells each */
#define GSTEP  8
#define GL     32
#define GR     64
#define NG     96
#define EXT    (GL+CHUNK+GR)   /* 1120 */
#define ROWSZ  (EXT+4)         /* 2 front pads + cells + 2 back pads = 1124 */
#define XB     512             /* X duty threads [512,768) */
#define GTB    768             /* ghost threads [768,816): 48 threads, 2 cells each */
#define NGT    48

typedef unsigned long long u64;

__device__ __forceinline__ uint32_t s2u(const void* p){
    return (uint32_t)__cvta_generic_to_shared(p);
}
__device__ __forceinline__ uint32_t mapa_u32(uint32_t la, uint32_t rank){
    uint32_t ra;
    asm("mapa.shared::cluster.u32 %0, %1, %2;" : "=r"(ra) : "r"(la), "r"(rank));
    return ra;
}
__device__ __forceinline__ void mbar_init(uint32_t a, uint32_t cnt){
    asm volatile("mbarrier.init.shared.b64 [%0], %1;" :: "r"(a), "r"(cnt) : "memory");
}
__device__ __forceinline__ void remote_st64(uint32_t ra, u64 v){
    asm volatile("st.shared::cluster.b64 [%0], %1;" :: "r"(ra), "l"(v) : "memory");
}
__device__ __forceinline__ void remote_arrive(uint32_t ra){
    asm volatile("mbarrier.arrive.release.cluster.shared::cluster.b64 _, [%0];"
                 :: "r"(ra) : "memory");
}
__device__ __forceinline__ void mbar_wait(uint32_t a, uint32_t parity){
    asm volatile(
        "{\n\t"
        ".reg .pred P;\n"
        "WL_%=:\n\t"
        "mbarrier.try_wait.parity.acquire.cluster.shared::cta.b64 P, [%0], %1;\n\t"
        "@!P bra WL_%=;\n\t"
        "}"
        :: "r"(a), "r"(parity) : "memory");
}

// ---- packed f32x2 helpers (each = two independent IEEE RN fp32 ops) ----
__device__ __forceinline__ u64 PK(float lo, float hi){
    u64 r; asm("mov.b64 %0, {%1, %2};" : "=l"(r) : "f"(lo), "f"(hi)); return r;
}
__device__ __forceinline__ float2 UP(u64 v){
    float2 r; asm("mov.b64 {%0, %1}, %2;" : "=f"(r.x), "=f"(r.y) : "l"(v)); return r;
}
__device__ __forceinline__ u64 pmul(u64 a, u64 b){
    u64 r; asm("mul.rn.f32x2 %0, %1, %2;" : "=l"(r) : "l"(a), "l"(b)); return r;
}
__device__ __forceinline__ u64 padd(u64 a, u64 b){
    u64 r; asm("add.rn.f32x2 %0, %1, %2;" : "=l"(r) : "l"(a), "l"(b)); return r;
}
__device__ __forceinline__ u64 pfma(u64 a, u64 b, u64 c){
    u64 r; asm("fma.rn.f32x2 %0, %1, %2, %3;" : "=l"(r) : "l"(a), "l"(b), "l"(c)); return r;
}

__global__ __launch_bounds__(NTH, 1) __cluster_dims__(CSZ, 1, 1)
void lorenz96_kernel(const float* __restrict__ X0,
                     const float* __restrict__ Y0,
                     const float* __restrict__ coupling,
                     const float* __restrict__ pF,
                     const float* __restrict__ ph,
                     const float* __restrict__ pc,
                     const float* __restrict__ pdt,
                     float* __restrict__ xhist,
                     float* __restrict__ yhist)
{
    __shared__ __align__(16) float sYe[2][ROWSZ]; // pos = 2 + cell_index
    __shared__ float sX [2][KXV];
    __shared__ __align__(8) float mbxL[2][GL];
    __shared__ __align__(8) float mbxR[2][GR];
    __shared__ __align__(8) unsigned long long mbarL[2];
    __shared__ __align__(8) unsigned long long mbarR[2];

    const int t = threadIdx.x;

    uint32_t rank;
    asm("mov.u32 %0, %%cluster_ctarank;" : "=r"(rank));
    const uint32_t lrank = (rank + CSZ - 1) % CSZ;
    const uint32_t rrank = (rank + 1) % CSZ;

    const float F  = *pF;
    const float h  = *ph;
    const float c  = *pc;
    const float dt = *pdt;

    // frozen bit-exact constant recipe
    const float a      = __fmul_rn(__fmul_rn(-1.0f, c), 32.0f);
    const float hcJ    = __fdiv_rn(__fmul_rn(h, c), 32.0f);
    const float halfdt = __fmul_rn(0.5f, dt);
    const float dt6    = __fdiv_rn(dt, 6.0f);

    // packed broadcast constants
    const u64 A2   = PK(a, a);
    const u64 NC2  = PK(-c, -c);          // (-c)*y == -(c*y) bit-exact
    const u64 HCJ2 = PK(hcJ, hcJ);
    const u64 M1   = PK(-1.0f, -1.0f);    // fma(-1,a,b) == b-a bit-exact
    const u64 HDT2 = PK(halfdt, halfdt);
    const u64 DT2  = PK(dt, dt);
    const u64 DT62 = PK(dt6, dt6);
    const u64 TWO2 = PK(2.0f, 2.0f);

    // duty assignment (all warp-uniform)
    const bool isY = (t < NYT);
    const int  jg  = (int)rank * CHUNK + 2 * t;      // first owned cell (Y threads)
    const int  xiO = jg >> 5;
    const int  pY  = 2 + GL + 2 * t;                 // sYe pos of own pair (even)

    const bool isXd = (t >= XB) && (t < XB + KXV);
    const int  xk   = t - XB;

    const int  gt   = t - GTB;
    const bool hasG = (t >= GTB) && (t < GTB + NGT);
    const bool gLft = hasG && (gt < GL / 2);
    const int  pG   = gLft ? (2 + 2 * gt) : (2 + GL + CHUNK + 2 * (gt - 16));
    const int  gg0  = gLft ? (((int)rank * CHUNK + NYV - GL + 2 * gt) & (NYV - 1))
                           : (((int)rank * CHUNK + CHUNK + 2 * (gt - 16)) & (NYV - 1));
    const int  xiG  = gg0 >> 5;

    if (t == 0) {
        #pragma unroll
        for (int b = 0; b < 2; b++) {
            mbar_init(s2u(&mbarL[b]), 16);   // 16 sender threads (pairs)
            mbar_init(s2u(&mbarR[b]), 32);   // 32 sender threads (pairs)
        }
        #pragma unroll
        for (int b = 0; b < 2; b++) {
            sYe[b][0] = 0.f; sYe[b][1] = 0.f;
            sYe[b][2 + EXT] = 0.f; sYe[b][3 + EXT] = 0.f;
        }
    }
    __syncthreads();
    asm volatile("barrier.cluster.arrive.aligned;" ::: "memory");
    asm volatile("barrier.cluster.wait.aligned;"   ::: "memory");

    // remote mailbox addresses (pair senders)
    uint32_t raR_d = 0, raR_b = 0, raL_d = 0, raL_b = 0;
    if (t < GR / 2) {                   // my first 64 cells -> LEFT neighbor's right ghosts
        raR_d = mapa_u32(s2u(&mbxR[0][2 * t]), lrank);
        raR_b = mapa_u32(s2u(&mbarR[0]),       lrank);
    }
    if (isY && t >= NYT - GL / 2) {     // my last 32 cells -> RIGHT neighbor's left ghosts
        raL_d = mapa_u32(s2u(&mbxL[0][2 * (t - (NYT - GL / 2))]), rrank);
        raL_b = mapa_u32(s2u(&mbarL[0]),                          rrank);
    }

    // ---- state init (row 0) ----
    float2 ycf = make_float2(0.f, 0.f);
    u64 ybp = 0, ycp = 0, d1p = 0, d2p = 0;
    if (isY) {
        ycf = *reinterpret_cast<const float2*>(&Y0[jg]);
        ycp = PK(ycf.x, ycf.y); ybp = ycp;
        *reinterpret_cast<float2*>(&yhist[jg]) = ycf;
        *reinterpret_cast<float2*>(&sYe[0][pY]) = ycf;
    }

    float2 gycf = make_float2(0.f, 0.f);
    u64 gybp = 0, gycp = 0, gd1p = 0, gd2p = 0;
    if (hasG) {
        gycf = *reinterpret_cast<const float2*>(&Y0[gg0]);
        gycp = PK(gycf.x, gycf.y); gybp = gycp;
        *reinterpret_cast<float2*>(&sYe[0][pG]) = gycf;
    }

    float xb = 0.f, xc = 0.f, xd1 = 0.f, xd2 = 0.f, coup_next = 0.f;
    if (isXd) {
        xb = X0[xk]; xc = xb;
        sX[0][xk] = xb;
        coup_next = coupling[xk];
        if (rank == 0) xhist[xk] = xb;
    }
    __syncthreads();

    int xrnd = 0;

    for (int n = 1; n < NTS; n++) {
        float coup = 0.f;
        if (isXd) {
            coup = coup_next;
            if (n < NTS - 1) coup_next = coupling[n * KXV + xk];
        }

        const bool     exch = ((n & (GSTEP - 1)) == 0) && (n < NTS - 1);
        const int      buf  = xrnd & 1;
        const uint32_t par  = (uint32_t)((xrnd >> 1) & 1);

        #pragma unroll
        for (int s = 0; s < 4; s++) {
            const int rb = s & 1;
            const int wb = rb ^ 1;

            if (isY) {
                const float2 l0 = *reinterpret_cast<const float2*>(&sYe[rb][pY - 2]); // cells e-2,e-1
                const float2 l2 = *reinterpret_cast<const float2*>(&sYe[rb][pY + 2]); // cells e+2,e+3
                const float  xs = sX[rb][xiO];
                const u64 ym1p = PK(l0.y, ycf.x);
                const u64 yp1p = PK(ycf.y, l2.x);
                const u64 yp2p = PK(l2.x, l2.y);
                const u64 xs2  = PK(xs, xs);
                // frozen recipe, packed: t1=yp2-ym1; t2=a*yp1; t4n=-(c*yc); t5=fma(t2,t1,t4n); dn=fma(hcJ,xs,t5)
                const u64 t1 = pfma(M1, ym1p, yp2p);
                const u64 t2 = pmul(A2, yp1p);
                const u64 t4n = pmul(NC2, ycp);
                const u64 t5 = pfma(t2, t1, t4n);
                const u64 dn = pfma(HCJ2, xs2, t5);

                if (s == 0)      { d1p = dn; ycp = pfma(HDT2, dn, ybp); }
                else if (s == 1) { d2p = dn; ycp = pfma(HDT2, dn, ybp); }
                else if (s == 2) { d2p = padd(d2p, dn); ycp = pfma(DT2, dn, ybp); }
                else {
                    const u64 sA  = padd(d1p, dn);
                    const u64 sum = pfma(TWO2, d2p, sA);
                    ycp = pfma(DT62, sum, ybp);
                    ybp = ycp;
                }
                ycf = UP(ycp);
                *reinterpret_cast<float2*>(&sYe[wb][pY]) = ycf;

                if (s == 3 && exch) {
                    if (t < GR / 2) {
                        remote_st64(raR_d + (uint32_t)buf * (GR * 4), ycp);
                        remote_arrive(raR_b + (uint32_t)buf * 8);
                    }
                    if (t >= NYT - GL / 2) {
                        remote_st64(raL_d + (uint32_t)buf * (GL * 4), ycp);
                        remote_arrive(raL_b + (uint32_t)buf * 8);
                    }
                }
            }
            else if (isXd) {
                const float xm2 = sX[rb][(xk + KXV - 2) & (KXV - 1)];
                const float xm1 = sX[rb][(xk + KXV - 1) & (KXV - 1)];
                const float xp1 = sX[rb][(xk + 1) & (KXV - 1)];
                const float u1 = __fsub_rn(xp1, xm2);
                const float u3 = __fmaf_rn(xm1, u1, -xc);
                const float u4 = __fadd_rn(u3, F);
                const float xdn = __fadd_rn(u4, coup);

                if (s == 0)      { xd1 = xdn; xc = __fmaf_rn(halfdt, xdn, xb); }
                else if (s == 1) { xd2 = xdn; xc = __fmaf_rn(halfdt, xdn, xb); }
                else if (s == 2) { xd2 = __fadd_rn(xd2, xdn); xc = __fmaf_rn(dt, xdn, xb); }
                else {
                    const float xA  = __fadd_rn(xd1, xdn);
                    const float xsm = __fmaf_rn(2.0f, xd2, xA);
                    xc = __fmaf_rn(dt6, xsm, xb);
                    xb = xc;
                }
                sX[wb][xk] = xc;
            }
            else if (hasG) {
                const float2 l0 = *reinterpret_cast<const float2*>(&sYe[rb][pG - 2]);
                const float2 l2 = *reinterpret_cast<const float2*>(&sYe[rb][pG + 2]);
                const float  xs = sX[rb][xiG];
                const u64 ym1p = PK(l0.y, gycf.x);
                const u64 yp1p = PK(gycf.y, l2.x);
                const u64 yp2p = PK(l2.x, l2.y);
                const u64 xs2  = PK(xs, xs);
                const u64 t1 = pfma(M1, ym1p, yp2p);
                const u64 t2 = pmul(A2, yp1p);
                const u64 t4n = pmul(NC2, gycp);
                const u64 t5 = pfma(t2, t1, t4n);
                const u64 dn = pfma(HCJ2, xs2, t5);

                if (s == 0)      { gd1p = dn; gycp = pfma(HDT2, dn, gybp); }
                else if (s == 1) { gd2p = dn; gycp = pfma(HDT2, dn, gybp); }
                else if (s == 2) { gd2p = padd(gd2p, dn); gycp = pfma(DT2, dn, gybp); }
                else {
                    const u64 sA  = padd(gd1p, dn);
                    const u64 sum = pfma(TWO2, gd2p, sA);
                    gycp = pfma(DT62, sum, gybp);
                    gybp = gycp;
                }
                gycf = UP(gycp);
                *reinterpret_cast<float2*>(&sYe[wb][pG]) = gycf;
            }
            __syncthreads();
        }

        // history row n (pair store)
        if (isY) *reinterpret_cast<float2*>(&yhist[(size_t)n * NYV + jg]) = ycf;
        if (isXd && rank == 0) xhist[(size_t)n * KXV + xk] = xc;

        // ghost receive every GSTEP steps
        if (exch) {
            if (hasG) {
                float2 gp;
                if (gLft) {
                    mbar_wait(s2u(&mbarL[buf]), par);
                    gp = *reinterpret_cast<const float2*>(&mbxL[buf][2 * gt]);
                } else {
                    mbar_wait(s2u(&mbarR[buf]), par);
                    gp = *reinterpret_cast<const float2*>(&mbxR[buf][2 * (gt - 16)]);
                }
                gycf = gp;
                gycp = PK(gp.x, gp.y);
                gybp = gycp;
                *reinterpret_cast<float2*>(&sYe[0][pG]) = gp;  // base buffer is buf0 at step start
            }
            xrnd++;
            __syncthreads();
        }
    }

    asm volatile("barrier.cluster.arrive.aligned;" ::: "memory");
    asm volatile("barrier.cluster.wait.aligned;"   ::: "memory");
}

extern "C" void kernel_launch(void* const* d_in, const int* in_sizes, int n_in,
                              void* d_out, int out_size)
{
    const float* X0  = (const float*)d_in[0];
    const float* Y0  = (const float*)d_in[1];
    const float* cp  = (const float*)d_in[2];
    const float* pF  = (const float*)d_in[3];
    const float* ph  = (const float*)d_in[4];
    // d_in[5] = b (unused by the math)
    const float* pc  = (const float*)d_in[6];
    const float* pdt = (const float*)d_in[7];

    float* out   = (float*)d_out;
    float* xhist = out;                       // [2048, 256]
    float* yhist = out + (size_t)NTS * KXV;   // [2048, 8192]

    lorenz96_kernel<<<CSZ, NTH>>>(X0, Y0, cp, pF, ph, pc, pdt, xhist, yhist);
}